// round 7
// baseline (speedup 1.0000x reference)
#include <cuda_runtime.h>
#include <math.h>

#define NN 50000
#define NE 600000
#define D  128
#define NH 3
#define BK 16

// ---------------- scratch (static device globals; no allocation) ----------------
__device__ __align__(16) float g_X1[(size_t)NN * D];        // x @ W_lin + b
__device__ __align__(16) float g_H[(size_t)NH * NN * D];    // per-head projections
__device__ float g_ssrc[NH * NN];                           // H @ att_src
__device__ float g_sdst[NH * NN];                           // H @ att_dst
__device__ float g_den[NH * NN];                            // softmax denominator
__device__ __align__(16) float g_ev[(size_t)NH * NE];       // per-edge exp(logit)
__device__ float g_ew[NE];                                  // edge weight
__device__ int   g_ei64;                                    // edge_index is int64?
__device__ int   g_eid64;                                   // edge_ids  is int64?

// dtype-robust index load
__device__ __forceinline__ int load_idx(const void* p, int is64, long long i) {
    if (is64) return (int)((const long long*)p)[i];
    return ((const int*)p)[i];
}

// cp.async 16B with zero-fill predicate
__device__ __forceinline__ void cp16(void* smem, const void* g, bool pred) {
    unsigned s = (unsigned)__cvta_generic_to_shared(smem);
    int bytes = pred ? 16 : 0;
    asm volatile("cp.async.cg.shared.global [%0], [%1], 16, %2;\n"
                 :: "r"(s), "l"(g), "r"(bytes));
}
__device__ __forceinline__ void cp_commit() {
    asm volatile("cp.async.commit_group;\n");
}
template <int N>
__device__ __forceinline__ void cp_wait() {
    asm volatile("cp.async.wait_group %0;\n" :: "n"(N));
}

// ---------------- dtype detection ----------------
__global__ void detect_dtype(const unsigned* __restrict__ ei_raw,
                             const unsigned* __restrict__ eid_raw) {
    int lane = threadIdx.x;                     // 64 threads
    unsigned a = ei_raw[2 * lane + 1];
    unsigned b = eid_raw[2 * lane + 1];
    unsigned ba = __ballot_sync(0xffffffffu, a == 0u);
    unsigned bb = __ballot_sync(0xffffffffu, b == 0u);
    __shared__ unsigned sa[2], sb[2];
    if ((threadIdx.x & 31) == 0) { sa[threadIdx.x >> 5] = ba; sb[threadIdx.x >> 5] = bb; }
    __syncthreads();
    if (threadIdx.x == 0) {
        g_ei64  = (sa[0] == 0xffffffffu && sa[1] == 0xffffffffu) ? 1 : 0;
        g_eid64 = (sb[0] == 0xffffffffu && sb[1] == 0xffffffffu) ? 1 : 0;
    }
}

// ---------------- init: out = mean(bias_heads), zero denominators ----------------
__global__ void __launch_bounds__(256) init_kernel(float* __restrict__ out,
                                                   const float* __restrict__ bh) {
    int i = blockIdx.x * 256 + threadIdx.x;
    if (i < NN * D) {
        int d = i & (D - 1);
        out[i] = (bh[d] + bh[D + d] + bh[2 * D + d]) * (1.0f / 3.0f);
    }
    if (i < NH * NN) g_den[i] = 0.0f;
}

// ---------------- fp32 GEMM: C[M,128] = A[M,128] @ B[128,128] (+bias) ----------------
// cp.async double-buffered, 128x128 tile, BK=16, 8x8 micro-tile, 256 threads.
// SCORES: fuse s_src/s_dst = row(C) . a vectors into the epilogue (head = blockIdx.y).
template <bool SCORES>
__global__ void __launch_bounds__(256, 2) gemm_k(
    const float* __restrict__ A, const float* __restrict__ B,
    const float* __restrict__ bias, float* __restrict__ C, int M,
    long long Bstride, long long Cstride,
    const float* __restrict__ asrc, const float* __restrict__ adst)
{
    __shared__ float As[2][128][BK];   // row-major A tile [m][k]
    __shared__ float Bs[2][BK][128];   // [k][n]

    const int h = blockIdx.y;
    B += (long long)h * Bstride;
    C += (long long)h * Cstride;

    const int tid  = threadIdx.x;
    const int tx   = tid & 15;
    const int ty   = tid >> 4;
    const int row0 = blockIdx.x * 128;

    // per-thread load slots
    const int ar0 = tid >> 1;                 // A slot 0: r in 0..127 (idx=tid)
    const int ak0 = (tid & 1) << 3;           //   wait: recompute properly below

    float acc[8][8];
#pragma unroll
    for (int i = 0; i < 8; i++)
#pragma unroll
        for (int j = 0; j < 8; j++) acc[i][j] = 0.0f;

    // A tile: 512 float4 slots -> 2 per thread: idx = tid, tid+256
    //   r = idx>>2, kq = (idx&3)*4
    // B tile: 512 float4 slots -> 2 per thread: kr = idx>>5, nq = (idx&31)*4
    auto load_tile = [&](int t, int buf) {
#pragma unroll
        for (int i = 0; i < 2; i++) {
            int idx = tid + i * 256;
            int r   = idx >> 2;
            int kq  = (idx & 3) << 2;
            int gr  = row0 + r;
            cp16(&As[buf][r][kq], A + (long long)gr * D + t * BK + kq, gr < M);
        }
#pragma unroll
        for (int i = 0; i < 2; i++) {
            int idx = tid + i * 256;
            int kr  = idx >> 5;
            int nq  = (idx & 31) << 2;
            cp16(&Bs[buf][kr][nq], B + (long long)(t * BK + kr) * D + nq, true);
        }
        cp_commit();
    };

    load_tile(0, 0);

#pragma unroll
    for (int t = 0; t < 8; t++) {
        int cur = t & 1;
        if (t < 7) load_tile(t + 1, cur ^ 1);
        if (t < 7) cp_wait<1>(); else cp_wait<0>();
        __syncthreads();

#pragma unroll
        for (int k = 0; k < BK; k++) {
            float a[8], b[8];
#pragma unroll
            for (int i = 0; i < 8; i++) a[i] = As[cur][ty * 8 + i][k];
            *(float4*)&b[0] = *(float4*)&Bs[cur][k][tx * 8];
            *(float4*)&b[4] = *(float4*)&Bs[cur][k][tx * 8 + 4];
#pragma unroll
            for (int i = 0; i < 8; i++)
#pragma unroll
                for (int j = 0; j < 8; j++)
                    acc[i][j] = fmaf(a[i], b[j], acc[i][j]);
        }
        __syncthreads();
    }
    (void)ar0; (void)ak0;

    float bv[8];
#pragma unroll
    for (int j = 0; j < 8; j++) bv[j] = bias ? bias[tx * 8 + j] : 0.0f;

#pragma unroll
    for (int i = 0; i < 8; i++) {
        int r = row0 + ty * 8 + i;
        if (r < M) {
            float4 o0 = make_float4(acc[i][0] + bv[0], acc[i][1] + bv[1],
                                    acc[i][2] + bv[2], acc[i][3] + bv[3]);
            float4 o1 = make_float4(acc[i][4] + bv[4], acc[i][5] + bv[5],
                                    acc[i][6] + bv[6], acc[i][7] + bv[7]);
            *(float4*)(C + (long long)r * D + tx * 8)     = o0;
            *(float4*)(C + (long long)r * D + tx * 8 + 4) = o1;
        }
    }

    if (SCORES) {
        // per-row dot with att vectors; reduce over the 16 tx lanes (same half-warp)
        float av[8], dv[8];
#pragma unroll
        for (int j = 0; j < 8; j++) {
            av[j] = asrc[h * D + tx * 8 + j];
            dv[j] = adst[h * D + tx * 8 + j];
        }
#pragma unroll
        for (int i = 0; i < 8; i++) {
            float s1 = 0.0f, s2 = 0.0f;
#pragma unroll
            for (int j = 0; j < 8; j++) {
                s1 = fmaf(acc[i][j], av[j], s1);
                s2 = fmaf(acc[i][j], dv[j], s2);
            }
#pragma unroll
            for (int o = 8; o; o >>= 1) {
                s1 += __shfl_xor_sync(0xffffffffu, s1, o);
                s2 += __shfl_xor_sync(0xffffffffu, s2, o);
            }
            int r = row0 + ty * 8 + i;
            if (tx == 0 && r < M) {
                g_ssrc[h * NN + r] = s1;
                g_sdst[h * NN + r] = s2;
            }
        }
    }
}

// ---------------- fused edge softmax pass (no segment max needed) ----------------
// softmax is shift-invariant; logits ~N(0,~1.5), max < ~12 => exp safely in fp32.
// One thread per edge handles all 3 heads; also precomputes edge weight.
__global__ void __launch_bounds__(256) edge_soft(
    const void* __restrict__ ei, const void* __restrict__ eids,
    const float* __restrict__ ddi, const float* __restrict__ eemb)
{
    int e = blockIdx.x * 256 + threadIdx.x;
    if (e >= NE) return;
    int is64 = g_ei64;
    int src = load_idx(ei, is64, e);
    int dst = load_idx(ei, is64, NE + e);
    g_ew[e] = __ldg(eemb + load_idx(eids, g_eid64, e)) - __ldg(ddi + e);
#pragma unroll
    for (int h = 0; h < NH; h++) {
        float v = g_ssrc[h * NN + src] + g_sdst[h * NN + dst];
        v = v > 0.0f ? v : 0.2f * v;                 // leaky_relu(0.2)
        float ex = __expf(v);
        g_ev[(size_t)h * NE + e] = ex;
        atomicAdd(&g_den[h * NN + dst], ex);
    }
}

// ---------------- fused 3-head weighted scatter ----------------
// one warp per edge; combine all heads in registers -> single red.v4 per lane.
__global__ void __launch_bounds__(256) edge_scatter(
    const void* __restrict__ ei, float* __restrict__ out)
{
    int w    = (blockIdx.x * 256 + threadIdx.x) >> 5;
    int lane = threadIdx.x & 31;
    if (w >= NE) return;
    int is64 = g_ei64;
    int src = load_idx(ei, is64, w);
    int dst = load_idx(ei, is64, NE + w);

    float cc = 0.0f;
    if (lane < NH) {
        float ex  = g_ev[(size_t)lane * NE + w];
        float den = fmaxf(g_den[lane * NN + dst], 1e-16f);
        cc = ex / den;
    } else if (lane == 3) {
        cc = g_ew[w] * (1.0f / 3.0f);
    }
    float c0 = __shfl_sync(0xffffffffu, cc, 0);
    float c1 = __shfl_sync(0xffffffffu, cc, 1);
    float c2 = __shfl_sync(0xffffffffu, cc, 2);
    float ew = __shfl_sync(0xffffffffu, cc, 3);
    c0 *= ew; c1 *= ew; c2 *= ew;

    float4 v0 = ((const float4*)(g_H + ((size_t)src) * D))[lane];
    float4 v1 = ((const float4*)(g_H + ((size_t)(NN + src)) * D))[lane];
    float4 v2 = ((const float4*)(g_H + ((size_t)(2 * NN + src)) * D))[lane];

    float4 r;
    r.x = fmaf(c2, v2.x, fmaf(c1, v1.x, c0 * v0.x));
    r.y = fmaf(c2, v2.y, fmaf(c1, v1.y, c0 * v0.y));
    r.z = fmaf(c2, v2.z, fmaf(c1, v1.z, c0 * v0.z));
    r.w = fmaf(c2, v2.w, fmaf(c1, v1.w, c0 * v0.w));

    float* op = out + (long long)dst * D + lane * 4;
    asm volatile("red.global.add.v4.f32 [%0], {%1,%2,%3,%4};"
                 :: "l"(op), "f"(r.x), "f"(r.y), "f"(r.z), "f"(r.w) : "memory");
}

// ---------------- launch ----------------
extern "C" void kernel_launch(void* const* d_in, const int* in_sizes, int n_in,
                              void* d_out, int out_size)
{
    const float* x    = (const float*)d_in[0];
    const void*  ei   = d_in[1];
    const void*  eids = d_in[2];
    const float* ddi  = (const float*)d_in[3];
    const float* Wlin = (const float*)d_in[4];
    const float* blin = (const float*)d_in[5];
    const float* eemb = (const float*)d_in[6];
    const float* Wh   = (const float*)d_in[7];
    const float* asrc = (const float*)d_in[8];
    const float* adst = (const float*)d_in[9];
    const float* bh   = (const float*)d_in[10];
    float* out = (float*)d_out;

    float *pX1 = nullptr, *pH = nullptr;
    cudaGetSymbolAddress((void**)&pX1, g_X1);
    cudaGetSymbolAddress((void**)&pH,  g_H);

    const int gemm_mblocks = (NN + 127) / 128;              // 391

    detect_dtype<<<1, 64>>>((const unsigned*)ei, (const unsigned*)eids);
    init_kernel<<<(NN * D + 255) / 256, 256>>>(out, bh);
    // X1 = x @ W_lin + b_lin
    gemm_k<false><<<gemm_mblocks, 256>>>(x, Wlin, blin, pX1, NN, 0, 0,
                                         nullptr, nullptr);
    // H_h = X1 @ W_h (3 heads) + fused attention scores
    gemm_k<true><<<dim3(gemm_mblocks, NH), 256>>>(pX1, Wh, nullptr, pH, NN,
                                                  (long long)D * D,
                                                  (long long)NN * D,
                                                  asrc, adst);
    edge_soft<<<(NE + 255) / 256, 256>>>(ei, eids, ddi, eemb);
    edge_scatter<<<(NE * 32 + 255) / 256, 256>>>(ei, out);
}

// round 8
// speedup vs baseline: 1.2409x; 1.2409x over previous
#include <cuda_runtime.h>
#include <math.h>

#define NN 50000
#define NE 600000
#define D  128
#define DD (D*D)
#define NH 3

// ---------------- scratch (static device globals; no allocation) ----------------
__device__ __align__(16) float g_H[(size_t)NH * NN * D];  // per-head projections
__device__ __align__(16) float g_Wc[NH * DD];             // W_lin @ W_h
__device__ __align__(16) float g_bvec[NH * D];            // b_lin @ W_h
__device__ __align__(16) float g_sc[NN * 8];              // [n]: s0 s1 s2 _ d0 d1 d2 _
__device__ __align__(16) float g_den[NN * 4];             // [n][h] softmax denom
__device__ __align__(16) float g_ev[(size_t)NE * 4];      // [e][h] exp(logit)
__device__ float g_ew[NE];                                // edge weight
__device__ int   g_ei64;                                  // edge_index is int64?
__device__ int   g_eid64;                                 // edge_ids  is int64?

// dtype-robust index load
__device__ __forceinline__ int load_idx(const void* p, int is64, long long i) {
    if (is64) return (int)((const long long*)p)[i];
    return ((const int*)p)[i];
}

// ---------------- dtype detection ----------------
__global__ void detect_dtype(const unsigned* __restrict__ ei_raw,
                             const unsigned* __restrict__ eid_raw) {
    int lane = threadIdx.x;                     // 64 threads
    unsigned a = ei_raw[2 * lane + 1];
    unsigned b = eid_raw[2 * lane + 1];
    unsigned ba = __ballot_sync(0xffffffffu, a == 0u);
    unsigned bb = __ballot_sync(0xffffffffu, b == 0u);
    __shared__ unsigned sa[2], sb[2];
    if ((threadIdx.x & 31) == 0) { sa[threadIdx.x >> 5] = ba; sb[threadIdx.x >> 5] = bb; }
    __syncthreads();
    if (threadIdx.x == 0) {
        g_ei64  = (sa[0] == 0xffffffffu && sa[1] == 0xffffffffu) ? 1 : 0;
        g_eid64 = (sb[0] == 0xffffffffu && sb[1] == 0xffffffffu) ? 1 : 0;
    }
}

// ---------------- init: out = mean(bias_heads), zero denominators ----------------
__global__ void __launch_bounds__(256) init_kernel(float* __restrict__ out,
                                                   const float* __restrict__ bh) {
    int i = blockIdx.x * 256 + threadIdx.x;
    if (i < NN * D) {
        int d = i & (D - 1);
        out[i] = (bh[d] + bh[D + d] + bh[2 * D + d]) * (1.0f / 3.0f);
    }
    if (i < NN * 4) g_den[i] = 0.0f;
}

// ---------------- bvec_h = b_lin @ W_h ----------------
__global__ void bvec_kernel(const float* __restrict__ blin,
                            const float* __restrict__ Wh) {
    int tid = blockIdx.x * 128 + threadIdx.x;     // 384 threads total
    int h = tid >> 7, j = tid & 127;
    if (h >= NH) return;
    float s = 0.0f;
    for (int k = 0; k < D; k++)
        s = fmaf(blin[k], Wh[h * DD + k * D + j], s);
    g_bvec[h * D + j] = s;
}

// ---------------- fp32 GEMM (R4-proven body): C[M,128] = A[M,128]@B[128,128] ----------------
// 256 threads, 128x128 tile, BK=16, 8x8 micro-tile, As transposed [k][m].
// SCORES: fuse scores (row . att vecs, incl. bias) into epilogue; head = blockIdx.y.
template <bool SCORES>
__global__ void __launch_bounds__(256) gemm_k(
    const float* __restrict__ A, const float* __restrict__ B,
    const float* __restrict__ bias, float* __restrict__ C, int M,
    long long Bstride, long long Cstride,
    const float* __restrict__ asrc, const float* __restrict__ adst)
{
    __shared__ float As[16][132];   // [k][m], padded
    __shared__ float Bs[16][128];   // [k][n]

    const int h = blockIdx.y;
    B += (long long)h * Bstride;
    C += (long long)h * Cstride;

    const int tid = threadIdx.x;
    const int tx  = tid & 15;
    const int ty  = tid >> 4;
    const int row0 = blockIdx.x * 128;

    float acc[8][8];
#pragma unroll
    for (int i = 0; i < 8; i++)
#pragma unroll
        for (int j = 0; j < 8; j++) acc[i][j] = 0.0f;

    for (int k0 = 0; k0 < 128; k0 += 16) {
#pragma unroll
        for (int i = 0; i < 2; i++) {
            int idx = tid + i * 256;          // 0..511 float4 slots
            int r   = idx >> 2;
            int kq  = (idx & 3) << 2;
            int gr  = row0 + r;
            float4 v = make_float4(0.f, 0.f, 0.f, 0.f);
            if (gr < M) v = *(const float4*)(A + (long long)gr * D + k0 + kq);
            As[kq + 0][r] = v.x; As[kq + 1][r] = v.y;
            As[kq + 2][r] = v.z; As[kq + 3][r] = v.w;
        }
#pragma unroll
        for (int i = 0; i < 2; i++) {
            int idx = tid + i * 256;
            int kr  = idx >> 5;
            int nq  = (idx & 31) << 2;
            *(float4*)&Bs[kr][nq] = *(const float4*)(B + (long long)(k0 + kr) * D + nq);
        }
        __syncthreads();

#pragma unroll
        for (int k = 0; k < 16; k++) {
            float a[8], b[8];
            *(float4*)&a[0] = *(float4*)&As[k][ty * 8];
            *(float4*)&a[4] = *(float4*)&As[k][ty * 8 + 4];
            *(float4*)&b[0] = *(float4*)&Bs[k][tx * 8];
            *(float4*)&b[4] = *(float4*)&Bs[k][tx * 8 + 4];
#pragma unroll
            for (int i = 0; i < 8; i++)
#pragma unroll
                for (int j = 0; j < 8; j++)
                    acc[i][j] = fmaf(a[i], b[j], acc[i][j]);
        }
        __syncthreads();
    }

    // add bias (per-head row vector) into acc, then store
    if (bias) {
        float bv[8];
#pragma unroll
        for (int j = 0; j < 8; j++) bv[j] = bias[h * D + tx * 8 + j];
#pragma unroll
        for (int i = 0; i < 8; i++)
#pragma unroll
            for (int j = 0; j < 8; j++) acc[i][j] += bv[j];
    }

#pragma unroll
    for (int i = 0; i < 8; i++) {
        int r = row0 + ty * 8 + i;
        if (r < M) {
            *(float4*)(C + (long long)r * D + tx * 8)     = *(float4*)&acc[i][0];
            *(float4*)(C + (long long)r * D + tx * 8 + 4) = *(float4*)&acc[i][4];
        }
    }

    if (SCORES) {
        float av[8], dv[8];
#pragma unroll
        for (int j = 0; j < 8; j++) {
            av[j] = asrc[h * D + tx * 8 + j];
            dv[j] = adst[h * D + tx * 8 + j];
        }
#pragma unroll
        for (int i = 0; i < 8; i++) {
            float s1 = 0.0f, s2 = 0.0f;
#pragma unroll
            for (int j = 0; j < 8; j++) {
                s1 = fmaf(acc[i][j], av[j], s1);
                s2 = fmaf(acc[i][j], dv[j], s2);
            }
#pragma unroll
            for (int o = 8; o; o >>= 1) {
                s1 += __shfl_xor_sync(0xffffffffu, s1, o);
                s2 += __shfl_xor_sync(0xffffffffu, s2, o);
            }
            int r = row0 + ty * 8 + i;
            if (tx == 0 && r < M) {
                g_sc[r * 8 + h]     = s1;
                g_sc[r * 8 + 4 + h] = s2;
            }
        }
    }
}

// ---------------- fused edge softmax pass (no segment max; logits are small) ----------------
__global__ void __launch_bounds__(256) edge_soft(
    const void* __restrict__ ei, const void* __restrict__ eids,
    const float* __restrict__ ddi, const float* __restrict__ eemb)
{
    int e = blockIdx.x * 256 + threadIdx.x;
    if (e >= NE) return;
    int is64 = g_ei64;
    int src = load_idx(ei, is64, e);
    int dst = load_idx(ei, is64, NE + e);
    g_ew[e] = __ldg(eemb + load_idx(eids, g_eid64, e)) - __ldg(ddi + e);

    float4 ss = *(const float4*)(g_sc + (size_t)src * 8);       // s0 s1 s2 _
    float4 dd = *(const float4*)(g_sc + (size_t)dst * 8 + 4);   // d0 d1 d2 _
    float v0 = ss.x + dd.x, v1 = ss.y + dd.y, v2 = ss.z + dd.z;
    v0 = v0 > 0.0f ? v0 : 0.2f * v0;
    v1 = v1 > 0.0f ? v1 : 0.2f * v1;
    v2 = v2 > 0.0f ? v2 : 0.2f * v2;
    float e0 = __expf(v0), e1 = __expf(v1), e2 = __expf(v2);
    *(float4*)(g_ev + (size_t)e * 4) = make_float4(e0, e1, e2, 0.0f);
    atomicAdd(&g_den[dst * 4 + 0], e0);
    atomicAdd(&g_den[dst * 4 + 1], e1);
    atomicAdd(&g_den[dst * 4 + 2], e2);
}

// ---------------- fused 3-head weighted scatter ----------------
// one warp per edge; combine heads in registers -> single red.v4 per lane.
__global__ void __launch_bounds__(256) edge_scatter(
    const void* __restrict__ ei, float* __restrict__ out)
{
    int w    = (blockIdx.x * 256 + threadIdx.x) >> 5;
    int lane = threadIdx.x & 31;
    if (w >= NE) return;
    int is64 = g_ei64;
    int src = load_idx(ei, is64, w);
    int dst = load_idx(ei, is64, NE + w);

    float cc = 0.0f;
    if (lane < NH) {
        float ex  = g_ev[(size_t)w * 4 + lane];
        float den = fmaxf(g_den[dst * 4 + lane], 1e-16f);
        cc = ex / den;
    } else if (lane == 3) {
        cc = g_ew[w] * (1.0f / 3.0f);
    }
    float c0 = __shfl_sync(0xffffffffu, cc, 0);
    float c1 = __shfl_sync(0xffffffffu, cc, 1);
    float c2 = __shfl_sync(0xffffffffu, cc, 2);
    float ew = __shfl_sync(0xffffffffu, cc, 3);
    c0 *= ew; c1 *= ew; c2 *= ew;

    float4 v0 = ((const float4*)(g_H + ((size_t)src) * D))[lane];
    float4 v1 = ((const float4*)(g_H + ((size_t)(NN + src)) * D))[lane];
    float4 v2 = ((const float4*)(g_H + ((size_t)(2 * NN + src)) * D))[lane];

    float4 r;
    r.x = fmaf(c2, v2.x, fmaf(c1, v1.x, c0 * v0.x));
    r.y = fmaf(c2, v2.y, fmaf(c1, v1.y, c0 * v0.y));
    r.z = fmaf(c2, v2.z, fmaf(c1, v1.z, c0 * v0.z));
    r.w = fmaf(c2, v2.w, fmaf(c1, v1.w, c0 * v0.w));

    float* op = out + (long long)dst * D + lane * 4;
    asm volatile("red.global.add.v4.f32 [%0], {%1,%2,%3,%4};"
                 :: "l"(op), "f"(r.x), "f"(r.y), "f"(r.z), "f"(r.w) : "memory");
}

// ---------------- launch ----------------
extern "C" void kernel_launch(void* const* d_in, const int* in_sizes, int n_in,
                              void* d_out, int out_size)
{
    const float* x    = (const float*)d_in[0];
    const void*  ei   = d_in[1];
    const void*  eids = d_in[2];
    const float* ddi  = (const float*)d_in[3];
    const float* Wlin = (const float*)d_in[4];
    const float* blin = (const float*)d_in[5];
    const float* eemb = (const float*)d_in[6];
    const float* Wh   = (const float*)d_in[7];
    const float* asrc = (const float*)d_in[8];
    const float* adst = (const float*)d_in[9];
    const float* bh   = (const float*)d_in[10];
    float* out = (float*)d_out;

    float *pWc = nullptr, *pH = nullptr;
    cudaGetSymbolAddress((void**)&pWc, g_Wc);
    cudaGetSymbolAddress((void**)&pH,  g_H);
    float *pBv = nullptr;
    cudaGetSymbolAddress((void**)&pBv, g_bvec);

    const int gemm_mblocks = (NN + 127) / 128;              // 391

    detect_dtype<<<1, 64>>>((const unsigned*)ei, (const unsigned*)eids);
    init_kernel<<<(NN * D + 255) / 256, 256>>>(out, bh);
    // W_comb_h = W_lin @ W_h  (tiny), bvec_h = b_lin @ W_h
    gemm_k<false><<<dim3(1, NH), 256>>>(Wlin, Wh, nullptr, pWc, D,
                                        (long long)DD, (long long)DD,
                                        nullptr, nullptr);
    bvec_kernel<<<3, 128>>>(blin, Wh);
    // H_h = x @ W_comb_h + bvec_h  (+ fused attention scores)
    gemm_k<true><<<dim3(gemm_mblocks, NH), 256>>>(x, pWc, pBv, pH, NN,
                                                  (long long)DD,
                                                  (long long)NN * D,
                                                  asrc, adst);
    edge_soft<<<(NE + 255) / 256, 256>>>(ei, eids, ddi, eemb);
    edge_scatter<<<(NE * 32 + 255) / 256, 256>>>(ei, out);
}

// round 11
// speedup vs baseline: 1.5764x; 1.2704x over previous
#include <cuda_runtime.h>
#include <cuda_fp16.h>
#include <math.h>

#define NN 50000
#define NE 600000
#define D  128
#define DD (D*D)
#define NH 3

// ---------------- scratch (static device globals; no allocation) ----------------
__device__ __align__(16) __half g_Hh[(size_t)NH * NN * D]; // per-head projections (fp16)
__device__ __align__(16) float  g_Wc[NH * DD];             // W_lin @ W_h
__device__ __align__(16) float  g_bvec[NH * D];            // b_lin @ W_h
__device__ __align__(16) float  g_sc[NN * 8];              // [n]: s0 s1 s2 _ d0 d1 d2 _
__device__ __align__(16) float  g_den[NN * 4];             // [n][h] softmax denom
__device__ __align__(16) float  g_ev[(size_t)NE * 4];      // [e][h] exp(logit)
__device__ float g_ew[NE];                                 // edge weight
__device__ int   g_ei64;                                   // edge_index is int64?
__device__ int   g_eid64;                                  // edge_ids  is int64?

// dtype-robust index load
__device__ __forceinline__ int load_idx(const void* p, int is64, long long i) {
    if (is64) return (int)((const long long*)p)[i];
    return ((const int*)p)[i];
}

// ---------------- dtype detection ----------------
__global__ void detect_dtype(const unsigned* __restrict__ ei_raw,
                             const unsigned* __restrict__ eid_raw) {
    int lane = threadIdx.x;                     // 64 threads
    unsigned a = ei_raw[2 * lane + 1];
    unsigned b = eid_raw[2 * lane + 1];
    unsigned ba = __ballot_sync(0xffffffffu, a == 0u);
    unsigned bb = __ballot_sync(0xffffffffu, b == 0u);
    __shared__ unsigned sa[2], sb[2];
    if ((threadIdx.x & 31) == 0) { sa[threadIdx.x >> 5] = ba; sb[threadIdx.x >> 5] = bb; }
    __syncthreads();
    if (threadIdx.x == 0) {
        g_ei64  = (sa[0] == 0xffffffffu && sa[1] == 0xffffffffu) ? 1 : 0;
        g_eid64 = (sb[0] == 0xffffffffu && sb[1] == 0xffffffffu) ? 1 : 0;
    }
}

// ---------------- init: out = mean(bias_heads), zero denominators ----------------
__global__ void __launch_bounds__(256) init_kernel(float* __restrict__ out,
                                                   const float* __restrict__ bh) {
    int i = blockIdx.x * 256 + threadIdx.x;
    if (i < NN * D) {
        int d = i & (D - 1);
        out[i] = (bh[d] + bh[D + d] + bh[2 * D + d]) * (1.0f / 3.0f);
    }
    if (i < NN * 4) g_den[i] = 0.0f;
}

// ---------------- prep: [Wlin; blin] (129x128) @ Wh_h -> g_Wc / g_bvec ----------------
// one thread per output element; 195 blocks -> full-chip latency hiding.
__global__ void __launch_bounds__(256) prep_kernel(const float* __restrict__ Wlin,
                                                   const float* __restrict__ blin,
                                                   const float* __restrict__ Wh) {
    int gid = blockIdx.x * 256 + threadIdx.x;
    int h   = blockIdx.y;
    if (gid >= 129 * D) return;
    int row = gid >> 7;            // 0..128 (128 == bias row)
    int col = gid & 127;
    const float* a = (row < 128) ? (Wlin + row * D) : blin;
    const float* b = Wh + h * DD + col;
    float s = 0.0f;
#pragma unroll 8
    for (int k = 0; k < D; k++)
        s = fmaf(a[k], b[(size_t)k * D], s);
    if (row < 128) g_Wc[h * DD + row * D + col] = s;
    else           g_bvec[h * D + col] = s;
}

// ---------------- fp32 GEMM: H_h[M,128] = x[M,128] @ Wc_h + bvec_h (half out) ------------
// 256 threads, 128x128 tile, BK=16, 8x8 micro-tile, As transposed [k][m].
// Fused epilogue: attention scores s_src/s_dst (fp32) + fp16 store of H.
__global__ void __launch_bounds__(256) gemm_k(
    const float* __restrict__ A, int M,
    const float* __restrict__ asrc, const float* __restrict__ adst)
{
    __shared__ float As[16][132];   // [k][m], padded
    __shared__ float Bs[16][128];   // [k][n]

    const int h = blockIdx.y;
    const float* B = g_Wc + (size_t)h * DD;

    const int tid = threadIdx.x;
    const int tx  = tid & 15;
    const int ty  = tid >> 4;
    const int row0 = blockIdx.x * 128;

    float acc[8][8];
#pragma unroll
    for (int i = 0; i < 8; i++)
#pragma unroll
        for (int j = 0; j < 8; j++) acc[i][j] = 0.0f;

    for (int k0 = 0; k0 < 128; k0 += 16) {
#pragma unroll
        for (int i = 0; i < 2; i++) {
            int idx = tid + i * 256;          // 0..511 float4 slots
            int r   = idx >> 2;
            int kq  = (idx & 3) << 2;
            int gr  = row0 + r;
            float4 v = make_float4(0.f, 0.f, 0.f, 0.f);
            if (gr < M) v = *(const float4*)(A + (long long)gr * D + k0 + kq);
            As[kq + 0][r] = v.x; As[kq + 1][r] = v.y;
            As[kq + 2][r] = v.z; As[kq + 3][r] = v.w;
        }
#pragma unroll
        for (int i = 0; i < 2; i++) {
            int idx = tid + i * 256;
            int kr  = idx >> 5;
            int nq  = (idx & 31) << 2;
            *(float4*)&Bs[kr][nq] = *(const float4*)(B + (long long)(k0 + kr) * D + nq);
        }
        __syncthreads();

#pragma unroll
        for (int k = 0; k < 16; k++) {
            float a[8], b[8];
            *(float4*)&a[0] = *(float4*)&As[k][ty * 8];
            *(float4*)&a[4] = *(float4*)&As[k][ty * 8 + 4];
            *(float4*)&b[0] = *(float4*)&Bs[k][tx * 8];
            *(float4*)&b[4] = *(float4*)&Bs[k][tx * 8 + 4];
#pragma unroll
            for (int i = 0; i < 8; i++)
#pragma unroll
                for (int j = 0; j < 8; j++)
                    acc[i][j] = fmaf(a[i], b[j], acc[i][j]);
        }
        __syncthreads();
    }

    // add bvec (part of h in the fused formulation)
    {
        float bv[8];
#pragma unroll
        for (int j = 0; j < 8; j++) bv[j] = g_bvec[h * D + tx * 8 + j];
#pragma unroll
        for (int i = 0; i < 8; i++)
#pragma unroll
            for (int j = 0; j < 8; j++) acc[i][j] += bv[j];
    }

    // fp16 store of H
    __half* Ch = g_Hh + (size_t)h * NN * D;
#pragma unroll
    for (int i = 0; i < 8; i++) {
        int r = row0 + ty * 8 + i;
        if (r < M) {
            __half2 p0 = __float22half2_rn(make_float2(acc[i][0], acc[i][1]));
            __half2 p1 = __float22half2_rn(make_float2(acc[i][2], acc[i][3]));
            __half2 p2 = __float22half2_rn(make_float2(acc[i][4], acc[i][5]));
            __half2 p3 = __float22half2_rn(make_float2(acc[i][6], acc[i][7]));
            uint4 u;
            u.x = *(unsigned*)&p0; u.y = *(unsigned*)&p1;
            u.z = *(unsigned*)&p2; u.w = *(unsigned*)&p3;
            *(uint4*)(Ch + (size_t)r * D + tx * 8) = u;
        }
    }

    // fused attention scores (fp32 acc)
    {
        float av[8], dv[8];
#pragma unroll
        for (int j = 0; j < 8; j++) {
            av[j] = asrc[h * D + tx * 8 + j];
            dv[j] = adst[h * D + tx * 8 + j];
        }
#pragma unroll
        for (int i = 0; i < 8; i++) {
            float s1 = 0.0f, s2 = 0.0f;
#pragma unroll
            for (int j = 0; j < 8; j++) {
                s1 = fmaf(acc[i][j], av[j], s1);
                s2 = fmaf(acc[i][j], dv[j], s2);
            }
#pragma unroll
            for (int o = 8; o; o >>= 1) {
                s1 += __shfl_xor_sync(0xffffffffu, s1, o);
                s2 += __shfl_xor_sync(0xffffffffu, s2, o);
            }
            int r = row0 + ty * 8 + i;
            if (tx == 0 && r < M) {
                g_sc[r * 8 + h]     = s1;
                g_sc[r * 8 + 4 + h] = s2;
            }
        }
    }
}

// ---------------- fused edge softmax pass (no segment max; logits are small) ----------------
__global__ void __launch_bounds__(256) edge_soft(
    const void* __restrict__ ei, const void* __restrict__ eids,
    const float* __restrict__ ddi, const float* __restrict__ eemb)
{
    int e = blockIdx.x * 256 + threadIdx.x;
    if (e >= NE) return;
    int is64 = g_ei64;
    int src = load_idx(ei, is64, e);
    int dst = load_idx(ei, is64, NE + e);
    g_ew[e] = __ldg(eemb + load_idx(eids, g_eid64, e)) - __ldg(ddi + e);

    float4 ss = *(const float4*)(g_sc + (size_t)src * 8);       // s0 s1 s2 _
    float4 dd = *(const float4*)(g_sc + (size_t)dst * 8 + 4);   // d0 d1 d2 _
    float v0 = ss.x + dd.x, v1 = ss.y + dd.y, v2 = ss.z + dd.z;
    v0 = v0 > 0.0f ? v0 : 0.2f * v0;
    v1 = v1 > 0.0f ? v1 : 0.2f * v1;
    v2 = v2 > 0.0f ? v2 : 0.2f * v2;
    float e0 = __expf(v0), e1 = __expf(v1), e2 = __expf(v2);
    *(float4*)(g_ev + (size_t)e * 4) = make_float4(e0, e1, e2, 0.0f);
    atomicAdd(&g_den[dst * 4 + 0], e0);
    atomicAdd(&g_den[dst * 4 + 1], e1);
    atomicAdd(&g_den[dst * 4 + 2], e2);
}

// ---------------- fused 3-head weighted scatter (fp16 gather, fp32 atomics) ----------------
__device__ __forceinline__ float4 loadH4(const __half* p) {
    uint2 u = *(const uint2*)p;
    __half2 a = *reinterpret_cast<__half2*>(&u.x);
    __half2 b = *reinterpret_cast<__half2*>(&u.y);
    float2 fa = __half22float2(a), fb = __half22float2(b);
    return make_float4(fa.x, fa.y, fb.x, fb.y);
}

__global__ void __launch_bounds__(256) edge_scatter(
    const void* __restrict__ ei, float* __restrict__ out)
{
    int w    = (blockIdx.x * 256 + threadIdx.x) >> 5;
    int lane = threadIdx.x & 31;
    if (w >= NE) return;
    int is64 = g_ei64;
    int src = load_idx(ei, is64, w);
    int dst = load_idx(ei, is64, NE + w);

    float cc = 0.0f;
    if (lane < NH) {
        float ex  = g_ev[(size_t)w * 4 + lane];
        float den = fmaxf(g_den[dst * 4 + lane], 1e-16f);
        cc = ex / den;
    } else if (lane == 3) {
        cc = g_ew[w] * (1.0f / 3.0f);
    }
    float c0 = __shfl_sync(0xffffffffu, cc, 0);
    float c1 = __shfl_sync(0xffffffffu, cc, 1);
    float c2 = __shfl_sync(0xffffffffu, cc, 2);
    float ew = __shfl_sync(0xffffffffu, cc, 3);
    c0 *= ew; c1 *= ew; c2 *= ew;

    const __half* h0 = g_Hh + (size_t)src * D + lane * 4;
    float4 v0 = loadH4(h0);
    float4 v1 = loadH4(h0 + (size_t)NN * D);
    float4 v2 = loadH4(h0 + (size_t)2 * NN * D);

    float4 r;
    r.x = fmaf(c2, v2.x, fmaf(c1, v1.x, c0 * v0.x));
    r.y = fmaf(c2, v2.y, fmaf(c1, v1.y, c0 * v0.y));
    r.z = fmaf(c2, v2.z, fmaf(c1, v1.z, c0 * v0.z));
    r.w = fmaf(c2, v2.w, fmaf(c1, v1.w, c0 * v0.w));

    float* op = out + (long long)dst * D + lane * 4;
    asm volatile("red.global.add.v4.f32 [%0], {%1,%2,%3,%4};"
                 :: "l"(op), "f"(r.x), "f"(r.y), "f"(r.z), "f"(r.w) : "memory");
}

// ---------------- launch ----------------
extern "C" void kernel_launch(void* const* d_in, const int* in_sizes, int n_in,
                              void* d_out, int out_size)
{
    const float* x    = (const float*)d_in[0];
    const void*  ei   = d_in[1];
    const void*  eids = d_in[2];
    const float* ddi  = (const float*)d_in[3];
    const float* Wlin = (const float*)d_in[4];
    const float* blin = (const float*)d_in[5];
    const float* eemb = (const float*)d_in[6];
    const float* Wh   = (const float*)d_in[7];
    const float* asrc = (const float*)d_in[8];
    const float* adst = (const float*)d_in[9];
    const float* bh   = (const float*)d_in[10];
    float* out = (float*)d_out;

    const int gemm_mblocks = (NN + 127) / 128;              // 391

    detect_dtype<<<1, 64>>>((const unsigned*)ei, (const unsigned*)eids);
    init_kernel<<<(NN * D + 255) / 256, 256>>>(out, bh);
    prep_kernel<<<dim3((129 * D + 255) / 256, NH), 256>>>(Wlin, blin, Wh);
    gemm_k<<<dim3(gemm_mblocks, NH), 256>>>(x, NN, asrc, adst);
    edge_soft<<<(NE + 255) / 256, 256>>>(ei, eids, ddi, eemb);
    edge_scatter<<<(NE * 32 + 255) / 256, 256>>>(ei, out);
}

// round 13
// speedup vs baseline: 1.9636x; 1.2456x over previous
#include <cuda_runtime.h>
#include <cuda_fp16.h>
#include <math.h>

#define NN 50000
#define NE 600000
#define D  128
#define DD (D*D)
#define NH 3

// ---------------- scratch (static device globals; no allocation) ----------------
__device__ __align__(16) __half g_Hh[(size_t)NH * NN * D]; // per-head projections (fp16)
__device__ __align__(16) float  g_Wc[NH * DD];             // W_lin @ W_h
__device__ __align__(16) float  g_bvec[NH * D];            // b_lin @ W_h
__device__ __align__(16) float  g_wv[6 * D];               // score vectors: Wc_h@a_{src,dst}
__device__ float  g_off[6];                                // score offsets: bvec_h . a
__device__ __align__(16) float  g_sc[NN * 8];              // [n]: s0 s1 s2 _ d0 d1 d2 _
__device__ __align__(16) float  g_den[NN * 4];             // [n][h] softmax denom
__device__ __align__(16) float  g_ev[(size_t)NE * 4];      // [e][h] exp(logit)
__device__ float g_ew[NE];                                 // edge weight
__device__ int   g_ei64;                                   // edge_index is int64?
__device__ int   g_eid64;                                  // edge_ids  is int64?

// dtype-robust index load
__device__ __forceinline__ int load_idx(const void* p, int is64, long long i) {
    if (is64) return (int)((const long long*)p)[i];
    return ((const int*)p)[i];
}

__device__ __forceinline__ unsigned f2tf32(float f) {
    unsigned u;
    asm("cvt.rna.tf32.f32 %0, %1;" : "=r"(u) : "f"(f));
    return u;
}

__device__ __forceinline__ void mma_tf32(float4& c, const unsigned* a, const unsigned* b) {
    asm volatile(
        "mma.sync.aligned.m16n8k8.row.col.f32.tf32.tf32.f32 "
        "{%0,%1,%2,%3}, {%4,%5,%6,%7}, {%8,%9}, {%0,%1,%2,%3};"
        : "+f"(c.x), "+f"(c.y), "+f"(c.z), "+f"(c.w)
        : "r"(a[0]), "r"(a[1]), "r"(a[2]), "r"(a[3]), "r"(b[0]), "r"(b[1]));
}

// ---------------- dtype detection ----------------
__global__ void detect_dtype(const unsigned* __restrict__ ei_raw,
                             const unsigned* __restrict__ eid_raw) {
    int lane = threadIdx.x;                     // 64 threads
    unsigned a = ei_raw[2 * lane + 1];
    unsigned b = eid_raw[2 * lane + 1];
    unsigned ba = __ballot_sync(0xffffffffu, a == 0u);
    unsigned bb = __ballot_sync(0xffffffffu, b == 0u);
    __shared__ unsigned sa[2], sb[2];
    if ((threadIdx.x & 31) == 0) { sa[threadIdx.x >> 5] = ba; sb[threadIdx.x >> 5] = bb; }
    __syncthreads();
    if (threadIdx.x == 0) {
        g_ei64  = (sa[0] == 0xffffffffu && sa[1] == 0xffffffffu) ? 1 : 0;
        g_eid64 = (sb[0] == 0xffffffffu && sb[1] == 0xffffffffu) ? 1 : 0;
    }
}

// ---------------- init: out = mean(bias_heads), zero denominators ----------------
__global__ void __launch_bounds__(256) init_kernel(float* __restrict__ out,
                                                   const float* __restrict__ bh) {
    int i = blockIdx.x * 256 + threadIdx.x;
    if (i < NN * D) {
        int d = i & (D - 1);
        out[i] = (bh[d] + bh[D + d] + bh[2 * D + d]) * (1.0f / 3.0f);
    }
    if (i < NN * 4) g_den[i] = 0.0f;
}

// ---------------- prep: [Wlin; blin] (129x128) @ Wh_h -> g_Wc / g_bvec ----------------
__global__ void __launch_bounds__(256) prep_kernel(const float* __restrict__ Wlin,
                                                   const float* __restrict__ blin,
                                                   const float* __restrict__ Wh) {
    int gid = blockIdx.x * 256 + threadIdx.x;
    int h   = blockIdx.y;
    if (gid >= 129 * D) return;
    int row = gid >> 7;            // 0..128 (128 == bias row)
    int col = gid & 127;
    const float* a = (row < 128) ? (Wlin + row * D) : blin;
    const float* b = Wh + h * DD + col;
    float s = 0.0f;
#pragma unroll 8
    for (int k = 0; k < D; k++)
        s = fmaf(a[k], b[(size_t)k * D], s);
    if (row < 128) g_Wc[h * DD + row * D + col] = s;
    else           g_bvec[h * D + col] = s;
}

// ---------------- prep2: score vectors wv[v][k] = Wc_h[k,:].a_v ; offsets ----------------
// v in 0..2 -> head v with a_src; v in 3..5 -> head v-3 with a_dst.  One warp/output.
__global__ void __launch_bounds__(256) prep2_kernel(const float* __restrict__ asrc,
                                                    const float* __restrict__ adst) {
    int w    = (blockIdx.x * 256 + threadIdx.x) >> 5;
    int lane = threadIdx.x & 31;
    if (w >= 6 * D + 6) return;
    const float* a;
    const float* row;
    int v;
    if (w < 6 * D) {
        v = w >> 7;
        int k = w & 127;
        int h = (v < 3) ? v : (v - 3);
        a   = (v < 3) ? (asrc + h * D) : (adst + (v - 3) * D);
        row = g_Wc + h * DD + (size_t)k * D;
    } else {
        v = w - 6 * D;
        int h = (v < 3) ? v : (v - 3);
        a   = (v < 3) ? (asrc + h * D) : (adst + (v - 3) * D);
        row = g_bvec + h * D;
    }
    float4 r4 = ((const float4*)row)[lane];
    float4 a4 = ((const float4*)a)[lane];
    float s = r4.x * a4.x + r4.y * a4.y + r4.z * a4.z + r4.w * a4.w;
#pragma unroll
    for (int o = 16; o; o >>= 1) s += __shfl_xor_sync(0xffffffffu, s, o);
    if (lane == 0) {
        if (w < 6 * D) g_wv[w] = s;
        else           g_off[v] = s;
    }
}

// ---------------- scores: g_sc[n] = { x[n].wv[0..2], x[n].wv[3..5] } + offsets ----------------
__global__ void __launch_bounds__(256) scores_k(const float* __restrict__ x, int M) {
    __shared__ float wv[6][128];
    __shared__ float off[8];
    for (int i = threadIdx.x; i < 6 * 128; i += 256) ((float*)wv)[i] = g_wv[i];
    if (threadIdx.x < 6) off[threadIdx.x] = g_off[threadIdx.x];
    __syncthreads();
    int n    = blockIdx.x * 8 + (threadIdx.x >> 5);
    int lane = threadIdx.x & 31;
    if (n >= M) return;
    float4 xv = *(const float4*)(x + (size_t)n * D + lane * 4);
    float s[6];
#pragma unroll
    for (int v = 0; v < 6; v++) {
        float4 w4 = ((const float4*)wv[v])[lane];
        float t = xv.x * w4.x + xv.y * w4.y + xv.z * w4.z + xv.w * w4.w;
#pragma unroll
        for (int o = 16; o; o >>= 1) t += __shfl_xor_sync(0xffffffffu, t, o);
        s[v] = t;
    }
    if (lane == 0) {
        *(float4*)(g_sc + (size_t)n * 8)     = make_float4(s[0] + off[0], s[1] + off[1], s[2] + off[2], 0.f);
        *(float4*)(g_sc + (size_t)n * 8 + 4) = make_float4(s[3] + off[3], s[4] + off[4], s[5] + off[5], 0.f);
    }
}

// ---------------- tf32 tensor-core GEMM: H_h = x @ Wc_h + bvec_h (fp16 out) ----------------
// CTA 128x128, BK=32, 8 warps (2 x 4), warp tile 64x32 = 4x4 m16n8 frags.
__global__ void __launch_bounds__(256, 2) gemm_tc(const float* __restrict__ A, int M) {
    __shared__ unsigned As[128][36];   // [m][k], pad 36 -> conflict-free frag loads
    __shared__ unsigned Bs[32][136];   // [k][n], pad 136 -> conflict-free frag loads

    const int h = blockIdx.y;
    const float* B = g_Wc + (size_t)h * DD;

    const int tid  = threadIdx.x;
    const int wid  = tid >> 5, lane = tid & 31;
    const int gid  = lane >> 2, tig = lane & 3;
    const int warp_m = (wid & 1) * 64;
    const int warp_n = (wid >> 1) * 32;
    const int row0 = blockIdx.x * 128;

    float4 acc[4][4];
#pragma unroll
    for (int i = 0; i < 4; i++)
#pragma unroll
        for (int j = 0; j < 4; j++) acc[i][j] = make_float4(0.f, 0.f, 0.f, 0.f);

    for (int t = 0; t < 4; t++) {
        const int k0 = t * 32;
        // A tile: 128x32 floats = 1024 float4 slots; 4 per thread
#pragma unroll
        for (int i = 0; i < 4; i++) {
            int idx = tid + i * 256;
            int r   = idx >> 3;
            int kq  = (idx & 7) << 2;
            int gr  = row0 + r;
            float4 v = (gr < M) ? *(const float4*)(A + (size_t)gr * D + k0 + kq)
                                : make_float4(0.f, 0.f, 0.f, 0.f);
            As[r][kq + 0] = f2tf32(v.x); As[r][kq + 1] = f2tf32(v.y);
            As[r][kq + 2] = f2tf32(v.z); As[r][kq + 3] = f2tf32(v.w);
        }
        // B tile: 32x128 floats = 1024 float4 slots; 4 per thread
#pragma unroll
        for (int i = 0; i < 4; i++) {
            int idx = tid + i * 256;
            int kr  = idx >> 5;
            int nq  = (idx & 31) << 2;
            float4 v = *(const float4*)(B + (size_t)(k0 + kr) * D + nq);
            Bs[kr][nq + 0] = f2tf32(v.x); Bs[kr][nq + 1] = f2tf32(v.y);
            Bs[kr][nq + 2] = f2tf32(v.z); Bs[kr][nq + 3] = f2tf32(v.w);
        }
        __syncthreads();

#pragma unroll
        for (int ks = 0; ks < 4; ks++) {
            const int k = ks * 8;
            unsigned a[4][4], b[4][2];
#pragma unroll
            for (int mi = 0; mi < 4; mi++) {
                int ar = warp_m + mi * 16 + gid;
                a[mi][0] = As[ar][k + tig];
                a[mi][1] = As[ar + 8][k + tig];
                a[mi][2] = As[ar][k + tig + 4];
                a[mi][3] = As[ar + 8][k + tig + 4];
            }
#pragma unroll
            for (int ni = 0; ni < 4; ni++) {
                int nb = warp_n + ni * 8 + gid;
                b[ni][0] = Bs[k + tig][nb];
                b[ni][1] = Bs[k + tig + 4][nb];
            }
#pragma unroll
            for (int mi = 0; mi < 4; mi++)
#pragma unroll
                for (int ni = 0; ni < 4; ni++)
                    mma_tf32(acc[mi][ni], a[mi], b[ni]);
        }
        __syncthreads();
    }

    // epilogue: + bvec, fp16 store
    __half* Ch = g_Hh + (size_t)h * NN * D;
#pragma unroll
    for (int ni = 0; ni < 4; ni++) {
        int c = warp_n + ni * 8 + 2 * tig;
        float bv0 = g_bvec[h * D + c];
        float bv1 = g_bvec[h * D + c + 1];
#pragma unroll
        for (int mi = 0; mi < 4; mi++) {
            int r = row0 + warp_m + mi * 16 + gid;
            float4 v = acc[mi][ni];
            if (r < M) {
                __half2 p = __float22half2_rn(make_float2(v.x + bv0, v.y + bv1));
                *(__half2*)(Ch + (size_t)r * D + c) = p;
            }
            if (r + 8 < M) {
                __half2 p = __float22half2_rn(make_float2(v.z + bv0, v.w + bv1));
                *(__half2*)(Ch + (size_t)(r + 8) * D + c) = p;
            }
        }
    }
}

// ---------------- fused edge softmax pass (no segment max; logits are small) ----------------
__global__ void __launch_bounds__(256) edge_soft(
    const void* __restrict__ ei, const void* __restrict__ eids,
    const float* __restrict__ ddi, const float* __restrict__ eemb)
{
    int e = blockIdx.x * 256 + threadIdx.x;
    if (e >= NE) return;
    int is64 = g_ei64;
    int src = load_idx(ei, is64, e);
    int dst = load_idx(ei, is64, NE + e);
    g_ew[e] = __ldg(eemb + load_idx(eids, g_eid64, e)) - __ldg(ddi + e);

    float4 ss = *(const float4*)(g_sc + (size_t)src * 8);       // s0 s1 s2 _
    float4 dd = *(const float4*)(g_sc + (size_t)dst * 8 + 4);   // d0 d1 d2 _
    float v0 = ss.x + dd.x, v1 = ss.y + dd.y, v2 = ss.z + dd.z;
    v0 = v0 > 0.0f ? v0 : 0.2f * v0;
    v1 = v1 > 0.0f ? v1 : 0.2f * v1;
    v2 = v2 > 0.0f ? v2 : 0.2f * v2;
    float e0 = __expf(v0), e1 = __expf(v1), e2 = __expf(v2);
    *(float4*)(g_ev + (size_t)e * 4) = make_float4(e0, e1, e2, 0.0f);
    atomicAdd(&g_den[dst * 4 + 0], e0);
    atomicAdd(&g_den[dst * 4 + 1], e1);
    atomicAdd(&g_den[dst * 4 + 2], e2);
}

// ---------------- fused 3-head weighted scatter (fp16 gather, fp32 atomics) ----------------
__device__ __forceinline__ float4 loadH4(const __half* p) {
    uint2 u = *(const uint2*)p;
    __half2 a = *reinterpret_cast<__half2*>(&u.x);
    __half2 b = *reinterpret_cast<__half2*>(&u.y);
    float2 fa = __half22float2(a), fb = __half22float2(b);
    return make_float4(fa.x, fa.y, fb.x, fb.y);
}

__global__ void __launch_bounds__(256) edge_scatter(
    const void* __restrict__ ei, float* __restrict__ out)
{
    int w    = (blockIdx.x * 256 + threadIdx.x) >> 5;
    int lane = threadIdx.x & 31;
    if (w >= NE) return;
    int is64 = g_ei64;
    int src = load_idx(ei, is64, w);
    int dst = load_idx(ei, is64, NE + w);

    float cc = 0.0f;
    if (lane < NH) {
        float ex  = g_ev[(size_t)w * 4 + lane];
        float den = fmaxf(g_den[dst * 4 + lane], 1e-16f);
        cc = ex / den;
    } else if (lane == 3) {
        cc = g_ew[w] * (1.0f / 3.0f);
    }
    float c0 = __shfl_sync(0xffffffffu, cc, 0);
    float c1 = __shfl_sync(0xffffffffu, cc, 1);
    float c2 = __shfl_sync(0xffffffffu, cc, 2);
    float ew = __shfl_sync(0xffffffffu, cc, 3);
    c0 *= ew; c1 *= ew; c2 *= ew;

    const __half* h0 = g_Hh + (size_t)src * D + lane * 4;
    float4 v0 = loadH4(h0);
    float4 v1 = loadH4(h0 + (size_t)NN * D);
    float4 v2 = loadH4(h0 + (size_t)2 * NN * D);

    float4 r;
    r.x = fmaf(c2, v2.x, fmaf(c1, v1.x, c0 * v0.x));
    r.y = fmaf(c2, v2.y, fmaf(c1, v1.y, c0 * v0.y));
    r.z = fmaf(c2, v2.z, fmaf(c1, v1.z, c0 * v0.z));
    r.w = fmaf(c2, v2.w, fmaf(c1, v1.w, c0 * v0.w));

    float* op = out + (long long)dst * D + lane * 4;
    asm volatile("red.global.add.v4.f32 [%0], {%1,%2,%3,%4};"
                 :: "l"(op), "f"(r.x), "f"(r.y), "f"(r.z), "f"(r.w) : "memory");
}

// ---------------- launch ----------------
extern "C" void kernel_launch(void* const* d_in, const int* in_sizes, int n_in,
                              void* d_out, int out_size)
{
    const float* x    = (const float*)d_in[0];
    const void*  ei   = d_in[1];
    const void*  eids = d_in[2];
    const float* ddi  = (const float*)d_in[3];
    const float* Wlin = (const float*)d_in[4];
    const float* blin = (const float*)d_in[5];
    const float* eemb = (const float*)d_in[6];
    const float* Wh   = (const float*)d_in[7];
    const float* asrc = (const float*)d_in[8];
    const float* adst = (const float*)d_in[9];
    const float* bh   = (const float*)d_in[10];
    float* out = (float*)d_out;

    const int gemm_mblocks = (NN + 127) / 128;              // 391

    detect_dtype<<<1, 64>>>((const unsigned*)ei, (const unsigned*)eids);
    init_kernel<<<(NN * D + 255) / 256, 256>>>(out, bh);
    prep_kernel<<<dim3((129 * D + 255) / 256, NH), 256>>>(Wlin, blin, Wh);
    prep2_kernel<<<((6 * D + 6) * 32 + 255) / 256, 256>>>(asrc, adst);
    scores_k<<<(NN + 7) / 8, 256>>>(x, NN);
    gemm_tc<<<dim3(gemm_mblocks, NH), 256>>>(x, NN);
    edge_soft<<<(NE + 255) / 256, 256>>>(ei, eids, ddi, eemb);
    edge_scatter<<<(NE * 32 + 255) / 256, 256>>>(ei, out);
}